// round 1
// baseline (speedup 1.0000x reference)
#include <cuda_runtime.h>
#include <cuda_bf16.h>
#include <mma.h>

using namespace nvcuda;

#define NN  512
#define BSZ 64
#define TT  200
#define DD  32

static constexpr size_t MAT = (size_t)BSZ * NN * NN;   // 16,777,216 elements

// Scratch (device globals: allocation-free rule)
__device__ __nv_bfloat16 g_P[MAT];   // A1/n in bf16
__device__ __nv_bfloat16 g_Q[MAT];   // P^2
__device__ __nv_bfloat16 g_M[MAT];   // P + P^2 + P^3

// ---------------------------------------------------------------------------
// Convert: P = bf16(adj * (1/512))
// ---------------------------------------------------------------------------
__global__ void k_convert(const float* __restrict__ adj, __nv_bfloat16* __restrict__ P) {
    size_t i = ((size_t)blockIdx.x * blockDim.x + threadIdx.x) * 4;
    float4 v = *(const float4*)(adj + i);
    const float s = 1.0f / 512.0f;
    __nv_bfloat162 p0 = __floats2bfloat162_rn(v.x * s, v.y * s);
    __nv_bfloat162 p1 = __floats2bfloat162_rn(v.z * s, v.w * s);
    uint2 u;
    u.x = *(unsigned*)&p0;
    u.y = *(unsigned*)&p1;
    *(uint2*)(P + i) = u;
}

// ---------------------------------------------------------------------------
// M = bf16(M + P + Q)   (M holds Q@P after second GEMM)
// ---------------------------------------------------------------------------
__device__ __forceinline__ float2 bf2_to_f2(unsigned u) {
    __nv_bfloat162 h = *(__nv_bfloat162*)&u;
    return make_float2(__low2float(h), __high2float(h));
}

__global__ void k_add(__nv_bfloat16* __restrict__ M,
                      const __nv_bfloat16* __restrict__ P,
                      const __nv_bfloat16* __restrict__ Q) {
    size_t i = ((size_t)blockIdx.x * blockDim.x + threadIdx.x) * 4;
    uint2 um = *(uint2*)(M + i);
    uint2 up = *(const uint2*)(P + i);
    uint2 uq = *(const uint2*)(Q + i);
    float2 m0 = bf2_to_f2(um.x), m1 = bf2_to_f2(um.y);
    float2 p0 = bf2_to_f2(up.x), p1 = bf2_to_f2(up.y);
    float2 q0 = bf2_to_f2(uq.x), q1 = bf2_to_f2(uq.y);
    __nv_bfloat162 r0 = __floats2bfloat162_rn(m0.x + p0.x + q0.x, m0.y + p0.y + q0.y);
    __nv_bfloat162 r1 = __floats2bfloat162_rn(m1.x + p1.x + q1.x, m1.y + p1.y + q1.y);
    uint2 u;
    u.x = *(unsigned*)&r0;
    u.y = *(unsigned*)&r1;
    *(uint2*)(M + i) = u;
}

// ---------------------------------------------------------------------------
// Batched bf16 GEMM: C[b] = A[b] @ B[b], 512x512x512, fp32 accum, bf16 out.
// Block tile 128x128, BK=64, 8 warps (each 32x64), cp.async double buffer.
// ---------------------------------------------------------------------------
__device__ __forceinline__ void cp16(void* s, const void* g) {
    unsigned sa = (unsigned)__cvta_generic_to_shared(s);
    asm volatile("cp.async.cg.shared.global [%0], [%1], 16;\n" :: "r"(sa), "l"(g));
}

__global__ void __launch_bounds__(256) k_gemm(const __nv_bfloat16* __restrict__ A,
                                              const __nv_bfloat16* __restrict__ B,
                                              __nv_bfloat16* __restrict__ C) {
    extern __shared__ __nv_bfloat16 smg[];
    __nv_bfloat16* As = smg;                 // [2][128*64]
    __nv_bfloat16* Bs = smg + 2 * 128 * 64;  // [2][64*128]

    const int tid = threadIdx.x;
    const int b   = blockIdx.z;
    const int bm0 = blockIdx.y * 128;
    const int bn0 = blockIdx.x * 128;
    const __nv_bfloat16* Ab = A + (size_t)b * NN * NN;
    const __nv_bfloat16* Bb = B + (size_t)b * NN * NN;

    const int ar = tid >> 3, ac = (tid & 7) * 8;     // A tile: 128 rows x 64 cols
    const int br = tid >> 4, bc = (tid & 15) * 8;    // B tile:  64 rows x 128 cols

    auto load_tiles = [&](int st, int k0) {
        __nv_bfloat16* a  = As + st * 8192;
        __nv_bfloat16* bt = Bs + st * 8192;
#pragma unroll
        for (int rr = 0; rr < 128; rr += 32)
            cp16(a + (ar + rr) * 64 + ac, Ab + (size_t)(bm0 + ar + rr) * NN + k0 + ac);
#pragma unroll
        for (int rr = 0; rr < 64; rr += 16)
            cp16(bt + (br + rr) * 128 + bc, Bb + (size_t)(k0 + br + rr) * NN + bn0 + bc);
        asm volatile("cp.async.commit_group;\n");
    };

    const int w  = tid >> 5;
    const int wm = w >> 1;   // 0..3
    const int wn = w & 1;    // 0..1

    wmma::fragment<wmma::accumulator, 16, 16, 16, float> cf[2][4];
#pragma unroll
    for (int i = 0; i < 2; i++)
#pragma unroll
        for (int j = 0; j < 4; j++) wmma::fill_fragment(cf[i][j], 0.0f);

    load_tiles(0, 0);
#pragma unroll
    for (int kt = 0; kt < 8; ++kt) {
        asm volatile("cp.async.wait_group 0;\n");
        __syncthreads();
        if (kt < 7) load_tiles((kt + 1) & 1, (kt + 1) * 64);
        const __nv_bfloat16* a  = As + (kt & 1) * 8192;
        const __nv_bfloat16* bt = Bs + (kt & 1) * 8192;
#pragma unroll
        for (int kk = 0; kk < 4; ++kk) {
            wmma::fragment<wmma::matrix_a, 16, 16, 16, __nv_bfloat16, wmma::row_major> af[2];
            wmma::fragment<wmma::matrix_b, 16, 16, 16, __nv_bfloat16, wmma::row_major> bfr[4];
#pragma unroll
            for (int i = 0; i < 2; i++)
                wmma::load_matrix_sync(af[i], a + (wm * 32 + i * 16) * 64 + kk * 16, 64);
#pragma unroll
            for (int j = 0; j < 4; j++)
                wmma::load_matrix_sync(bfr[j], bt + (kk * 16) * 128 + wn * 64 + j * 16, 128);
#pragma unroll
            for (int i = 0; i < 2; i++)
#pragma unroll
                for (int j = 0; j < 4; j++)
                    wmma::mma_sync(cf[i][j], af[i], bfr[j], cf[i][j]);
        }
        __syncthreads();
    }

    // Epilogue: spill accumulators to smem (reuse 64KB), convert to bf16
    float* Cs = (float*)smg;
#pragma unroll
    for (int i = 0; i < 2; i++)
#pragma unroll
        for (int j = 0; j < 4; j++)
            wmma::store_matrix_sync(Cs + (wm * 32 + i * 16) * 128 + wn * 64 + j * 16,
                                    cf[i][j], 128, wmma::mem_row_major);
    __syncthreads();

    int rl = tid >> 1, half = tid & 1;
    __nv_bfloat16* Cg = C + (size_t)b * NN * NN + (size_t)(bm0 + rl) * NN + bn0 + half * 64;
    const float* src = Cs + rl * 128 + half * 64;
#pragma unroll
    for (int c = 0; c < 64; c += 4) {
        float4 v = *(const float4*)(src + c);
        __nv_bfloat162 p0 = __floats2bfloat162_rn(v.x, v.y);
        __nv_bfloat162 p1 = __floats2bfloat162_rn(v.z, v.w);
        uint2 u;
        u.x = *(unsigned*)&p0;
        u.y = *(unsigned*)&p1;
        *(uint2*)(Cg + c) = u;
    }
}

// ---------------------------------------------------------------------------
// Persistent scan: one CTA per batch, 512 threads, 199 sequential steps.
// All weights + node embeddings + state live in shared memory.
// ---------------------------------------------------------------------------
// smem layout (float offsets)
#define OFF_NREC  0        // [32][512]
#define OFF_NSEND 16384    // [32][512]
#define OFF_LP    32768    // [2][512]
#define OFF_NLF   33792    // [2][512]
#define OFF_LP2   34816    // [512] unsigned (bf16x2 dup of lp)
#define OFF_PART  35328    // [4][512]
#define OFF_UB    37376    // [2][32]
#define OFF_UF    37440    // [2][32]
#define OFF_H     37504    // [32]
#define OFF_UU    37536    // [32]
#define OFF_W1    37568    // [160][32]
#define OFF_W2    42688    // [32][32]
#define OFF_WF    43712    // [32][32]
#define OFF_WB    44736    // [32][32]
#define OFF_B1    45760
#define OFF_B2    45792
#define OFF_BFB   45824
#define OFF_BBB   45856
#define SCAN_SMEM_FLOATS 45888
#define SCAN_SMEM_BYTES  (SCAN_SMEM_FLOATS * 4)

__global__ void __launch_bounds__(512, 1) k_scan(
    const int* __restrict__ skills, const int* __restrict__ times_,
    const float* __restrict__ labels, const float* __restrict__ nemb,
    const float* __restrict__ ub0, const float* __restrict__ uf0,
    const float* __restrict__ cw1, const float* __restrict__ cb1,
    const float* __restrict__ cw2, const float* __restrict__ cb2,
    const float* __restrict__ lfw, const float* __restrict__ lfb,
    const float* __restrict__ lbw, const float* __restrict__ lbb,
    const __nv_bfloat16* __restrict__ Mg, float* __restrict__ out) {

    extern __shared__ float smf[];
    float*    nrec  = smf + OFF_NREC;
    float*    nsend = smf + OFF_NSEND;
    float*    lp    = smf + OFF_LP;
    float*    nlf   = smf + OFF_NLF;
    unsigned* lp2   = (unsigned*)(smf + OFF_LP2);
    float*    part  = smf + OFF_PART;
    float*    ub    = smf + OFF_UB;
    float*    uf    = smf + OFF_UF;
    float*    hbuf  = smf + OFF_H;
    float*    uubuf = smf + OFF_UU;
    float*    w1t   = smf + OFF_W1;
    float*    w2t   = smf + OFF_W2;
    float*    wft   = smf + OFF_WF;
    float*    wbt   = smf + OFF_WB;
    float*    b1s   = smf + OFF_B1;
    float*    b2s   = smf + OFF_B2;
    float*    bfs   = smf + OFF_BFB;
    float*    bbs   = smf + OFF_BBB;

    const int b   = blockIdx.x;
    const int tid = threadIdx.x;

    // ---- one-time init ----
    for (int i = tid; i < NN * DD; i += 512) {
        int k = i >> 5, d = i & 31;
        nsend[d * NN + k] = nemb[k * 64 + d];        // node_send = emb[:, :D]
        nrec[d * NN + k]  = nemb[k * 64 + 32 + d];   // node_rec  = emb[:, D:]
    }
    for (int i = tid; i < 5120; i += 512) {          // conv1_w (o,c,l) -> [c*5+l][o]
        int o = i / 160, r = i % 160;
        w1t[r * 32 + o] = cw1[i];
    }
    for (int i = tid; i < 1024; i += 512) {
        int o = i >> 5, r = i & 31;
        w2t[r * 32 + o] = cw2[i];
        wft[r * 32 + o] = lfw[i];
        wbt[r * 32 + o] = lbw[i];
    }
    if (tid < 32) {
        b1s[tid] = cb1[tid];  b2s[tid] = cb2[tid];
        bfs[tid] = lfb[tid];  bbs[tid] = lbb[tid];
        ub[tid]  = ub0[b * 32 + tid];
        uf[tid]  = uf0[b * 32 + tid];
    }
    __syncthreads();

    // carry init: last_perf0 = ub0 @ nrec^T, nlf0 = uf0 @ nsend^T
    {
        float l0 = 0.f, f0 = 0.f;
#pragma unroll
        for (int d = 0; d < 32; d++) {
            l0 += ub[d] * nrec[d * NN + tid];
            f0 += uf[d] * nsend[d * NN + tid];
        }
        lp[tid]  = l0;
        nlf[tid] = f0;
        __nv_bfloat162 dd = __float2bfloat162_rn(l0);
        lp2[tid] = *(unsigned*)&dd;
    }
    __syncthreads();

    const int jg = tid >> 7;        // 0..3 : j-chunk of 128
    const int kg = tid & 127;       // 0..127: 4 consecutive k columns
    const uint2* mbase = (const uint2*)(Mg + ((size_t)b << 18)) + jg * (128 * 128) + kg;

    const float inv1536 = 1.0f / 1536.0f;
    const float invlog5 = 0.6213349345596119f;   // 1/ln(5)

    for (int s = 0; s < TT - 1; ++s) {
        const int cp = s & 1, np = cp ^ 1;
        const int   skill = skills[b * TT + s + 1];
        const float lab   = labels[b * TT + s + 1];
        const float dtv   = fabsf((float)(times_[b * TT + s + 1] - times_[b * TT + s]));
        const float delta = logf(dtv + 1e-6f) * invlog5;

        // --- phase 1 (reads carry) ---
        float bse = 0.f, nn = 0.f;
#pragma unroll
        for (int d = 0; d < 32; d++) {
            bse += ub[cp * 32 + d] * nrec[d * NN + tid];
            nn  += uf[cp * 32 + d] * nsend[d * NN + tid];
        }
        const float tmp = expf(-delta * 0.1f * nlf[cp * NN + tid]) * lp[cp * NN + tid];

        // GEMV partials: this thread owns columns 4*kg..4*kg+3, j-range jg*128..+127
        __nv_bfloat162 a0 = __float2bfloat162_rn(0.f);
        __nv_bfloat162 a1 = a0;
        const unsigned* lps = lp2 + (jg << 7);
#pragma unroll 8
        for (int j = 0; j < 128; ++j) {
            uint2 mv = mbase[(size_t)j * 128];
            unsigned lv = lps[j];
            __nv_bfloat162 l2 = *(__nv_bfloat162*)&lv;
            a0 = __hfma2(l2, *(__nv_bfloat162*)&mv.x, a0);
            a1 = __hfma2(l2, *(__nv_bfloat162*)&mv.y, a1);
        }
        *(float4*)&part[jg * NN + (kg << 2)] =
            make_float4(__low2float(a0), __high2float(a0), __low2float(a1), __high2float(a1));

        __syncthreads();

        // --- phase 2 (writes next carry) ---
        const float spat = (part[tid] + part[NN + tid] + part[2 * NN + tid] + part[3 * NN + tid]) * inv1536;
        const float x    = bse + tmp + spat;
        const float cur  = 1.0f / (1.0f + expf(-x));
        lp[np * NN + tid]  = cur;
        nlf[np * NN + tid] = nn;
        __nv_bfloat162 cd = __float2bfloat162_rn(cur);
        lp2[tid] = *(unsigned*)&cd;
        if (tid == skill) out[s * BSZ + b] = cur;

        // tiny MLP on warp 0
        if (tid < 32) {
            const int o = tid;
            float hv = b1s[o];
#pragma unroll
            for (int c = 0; c < 32; ++c) {
                float u0 = ub[cp * 32 + c], u1 = uf[cp * 32 + c];
                float u3 = nrec[c * NN + skill], u4 = nsend[c * NN + skill];
                const float* w = w1t + c * 5 * 32 + o;
                hv += u0 * w[0] + u1 * w[32] + lab * w[64] + u3 * w[96] + u4 * w[128];
            }
            hbuf[o] = fmaxf(hv, 0.f);
            __syncwarp();
            float uu = b2s[o];
#pragma unroll
            for (int i2 = 0; i2 < 32; i2++) uu += hbuf[i2] * w2t[i2 * 32 + o];
            uubuf[o] = uu;
            __syncwarp();
            float af = bfs[o], ab = bbs[o];
#pragma unroll
            for (int i2 = 0; i2 < 32; i2++) {
                float u = uubuf[i2];
                af += u * wft[i2 * 32 + o];
                ab += u * wbt[i2 * 32 + o];
            }
            ub[np * 32 + o] = tanhf(ab);   // new user_b from lin_b
            uf[np * 32 + o] = tanhf(af);   // new user_f from lin_f
        }
        __syncthreads();
    }
}

// ---------------------------------------------------------------------------
extern "C" void kernel_launch(void* const* d_in, const int* in_sizes, int n_in,
                              void* d_out, int out_size) {
    const int*   skills = (const int*)  d_in[0];
    const int*   times_ = (const int*)  d_in[1];
    const float* labels = (const float*)d_in[2];
    const float* adj    = (const float*)d_in[3];
    const float* nemb   = (const float*)d_in[4];
    const float* ub0    = (const float*)d_in[5];
    const float* uf0    = (const float*)d_in[6];
    const float* cw1    = (const float*)d_in[7];
    const float* cb1    = (const float*)d_in[8];
    const float* cw2    = (const float*)d_in[9];
    const float* cb2    = (const float*)d_in[10];
    const float* lfw    = (const float*)d_in[11];
    const float* lfb    = (const float*)d_in[12];
    const float* lbw    = (const float*)d_in[13];
    const float* lbb    = (const float*)d_in[14];

    void *pP = nullptr, *pQ = nullptr, *pM = nullptr;
    cudaGetSymbolAddress(&pP, g_P);
    cudaGetSymbolAddress(&pQ, g_Q);
    cudaGetSymbolAddress(&pM, g_M);
    __nv_bfloat16* P = (__nv_bfloat16*)pP;
    __nv_bfloat16* Q = (__nv_bfloat16*)pQ;
    __nv_bfloat16* M = (__nv_bfloat16*)pM;

    cudaFuncSetAttribute(k_gemm, cudaFuncAttributeMaxDynamicSharedMemorySize, 65536);
    cudaFuncSetAttribute(k_scan, cudaFuncAttributeMaxDynamicSharedMemorySize, SCAN_SMEM_BYTES);

    // P = A1/n
    k_convert<<<16384, 256>>>(adj, P);
    // Q = P@P ; M(tmp) = Q@P ; M = P + Q + Q@P
    dim3 g(4, 4, 64);
    k_gemm<<<g, 256, 65536>>>(P, P, Q);
    k_gemm<<<g, 256, 65536>>>(Q, P, M);
    k_add<<<16384, 256>>>(M, P, Q);
    // persistent per-batch scan
    k_scan<<<BSZ, 512, SCAN_SMEM_BYTES>>>(skills, times_, labels, nemb, ub0, uf0,
                                          cw1, cb1, cw2, cb2, lfw, lfb, lbw, lbb,
                                          M, (float*)d_out);
}